// round 16
// baseline (speedup 1.0000x reference)
#include <cuda_runtime.h>

#define B_ 4
#define T_ 128
#define S_ 512
#define D_ 512

// Scratch (allocation-free rule: __device__ globals)
__device__ __align__(16) float g_wq [B_ * T_ * D_];          // 1 MB
__device__ __align__(16) float g_uh [B_ * S_ * D_];          // 4 MB
__device__ __align__(16) float g_pre[B_ * T_ * D_];          // 1 MB  inp @ WoutR^T + bout
__device__ __align__(16) float g_c  [B_ * T_ * D_];          // 1 MB  context vectors

__device__ __forceinline__ float fast_tanh(float x) {
    float y;
    asm("tanh.approx.f32 %0, %1;" : "=f"(y) : "f"(x));
    return y;
}

__device__ __forceinline__ unsigned cvt_bits_tf32(unsigned x) {
    unsigned u;
    asm("cvt.rna.tf32.f32 %0, %1;" : "=r"(u) : "f"(__uint_as_float(x)));
    return u;
}

__device__ __forceinline__ void mma_tf32(float* d, const unsigned* a, const unsigned* b) {
    asm volatile(
        "mma.sync.aligned.m16n8k8.row.col.f32.tf32.tf32.f32 "
        "{%0,%1,%2,%3}, {%4,%5,%6,%7}, {%8,%9}, {%0,%1,%2,%3};"
        : "+f"(d[0]), "+f"(d[1]), "+f"(d[2]), "+f"(d[3])
        : "r"(a[0]), "r"(a[1]), "r"(a[2]), "r"(a[3]), "r"(b[0]), "r"(b[1]));
}

__device__ __forceinline__ void ldsm_x4(unsigned& r0, unsigned& r1,
                                        unsigned& r2, unsigned& r3,
                                        unsigned addr) {
    asm volatile(
        "ldmatrix.sync.aligned.m8n8.x4.shared.b16 {%0,%1,%2,%3}, [%4];"
        : "=r"(r0), "=r"(r1), "=r"(r2), "=r"(r3) : "r"(addr));
}

__device__ __forceinline__ void cp_async16(unsigned saddr, const void* gptr) {
    asm volatile("cp.async.cg.shared.global [%0], [%1], 16;"
                 :: "r"(saddr), "l"(gptr));
}
__device__ __forceinline__ void cp_commit() {
    asm volatile("cp.async.commit_group;");
}
__device__ __forceinline__ void cp_wait2() {
    asm volatile("cp.async.wait_group 2;");
}
__device__ __forceinline__ void cp_wait1() {
    asm volatile("cp.async.wait_group 1;");
}

// Value-folding butterfly merge (verified R14): lane&mask==0 lanes own the
// lo value's pair-sum, set lanes own hi's.
__device__ __forceinline__ float merge2(float lo, float hi, int mask, int lane) {
    const bool up = (lane & mask) != 0;
    float mine  = up ? hi : lo;
    float other = up ? lo : hi;
    return mine + __shfl_xor_sync(0xFFFFFFFFu, other, mask);
}

// ---------------------------------------------------------------------------
// Segmented NT GEMM on tensor cores (tf32 HMMA, fp32 accumulate). R15 version.
// BM=BN=64, BK=16, 256 threads, warp tile m32 x n16, 4-stage cp.async.
// ---------------------------------------------------------------------------
struct GemmArgs {
    const float* A[3];
    const float* W[3];
    const float* bias[3];
    const float* addC[3];
    float*       C[3];
    int lda[3], ldw[3], ldc[3];
    int segEnd[3];
};

#define STAGES 4
#define STAGE_BYTES (64u * 20u * 4u)

__global__ __launch_bounds__(256) void gemm_seg_kernel(GemmArgs args, int K)
{
    __shared__ unsigned As[STAGES][64][20];
    __shared__ unsigned Ws[STAGES][64][20];

    const int bm = blockIdx.x;
    int seg = 0;
    if (bm >= args.segEnd[0]) seg = 1;
    if (bm >= args.segEnd[1]) seg = 2;
    const int segStart = (seg == 0) ? 0 : args.segEnd[seg - 1];

    const float* A    = args.A[seg];
    const float* W    = args.W[seg];
    const float* bias = args.bias[seg];
    const float* addC = args.addC[seg];
    float*       C    = args.C[seg];
    const int lda = args.lda[seg], ldw = args.ldw[seg], ldc = args.ldc[seg];

    const int m0 = (bm - segStart) * 64;
    const int n0 = blockIdx.y * 64;

    const int tid  = threadIdx.x;
    const int warp = tid >> 5;
    const int lane = tid & 31;
    const int wm   = warp >> 2;
    const int wn   = warp & 3;
    const int grp  = lane >> 2;
    const int qid  = lane & 3;

    const int lr = tid >> 2;
    const int lc = (tid & 3) * 4;

    const int q  = lane >> 3;
    const int qr = lane & 7;
    unsigned baseAs, baseWs;
    {
        unsigned a32 = (unsigned)__cvta_generic_to_shared(&As[0][0][0]);
        unsigned w32 = (unsigned)__cvta_generic_to_shared(&Ws[0][0][0]);
        const int arow = wm * 32 + (q & 1) * 8 + qr;
        const int acol = (q >> 1) * 4;
        baseAs = a32 + (unsigned)((arow * 20 + acol) * 4);
        const int brow = wn * 16 + (q >> 1) * 8 + qr;
        const int bcol = (q & 1) * 4;
        baseWs = w32 + (unsigned)((brow * 20 + bcol) * 4);
    }

    unsigned stA = (unsigned)__cvta_generic_to_shared(&As[0][lr][lc]);
    unsigned stW = (unsigned)__cvta_generic_to_shared(&Ws[0][lr][lc]);
    const float* Ag = A + (long)(m0 + lr) * lda + lc;
    const float* Wg = W + (long)(n0 + lr) * ldw + lc;
    const int nChunks = K / 16;

    float acc[2][2][4] = {};

    #pragma unroll
    for (int p = 0; p < STAGES - 1; p++) {
        if (p < nChunks) {
            cp_async16(stA + p * STAGE_BYTES, Ag + p * 16);
            cp_async16(stW + p * STAGE_BYTES, Wg + p * 16);
        }
        cp_commit();
    }

    for (int c = 0; c < nChunks; c++) {
        cp_wait2();
        __syncthreads();

        const int pf = c + STAGES - 1;
        if (pf < nChunks) {
            const unsigned so = (unsigned)(pf & (STAGES - 1)) * STAGE_BYTES;
            cp_async16(stA + so, Ag + pf * 16);
            cp_async16(stW + so, Wg + pf * 16);
        }
        cp_commit();

        const unsigned boff = (unsigned)(c & (STAGES - 1)) * STAGE_BYTES;
        #pragma unroll
        for (int s = 0; s < 2; s++) {
            const unsigned soff = boff + (unsigned)(s * 32);
            unsigned afr[2][4], bfr[4];
            ldsm_x4(afr[0][0], afr[0][1], afr[0][2], afr[0][3], baseAs + soff);
            ldsm_x4(afr[1][0], afr[1][1], afr[1][2], afr[1][3],
                    baseAs + soff + 16u * 20u * 4u);
            ldsm_x4(bfr[0], bfr[1], bfr[2], bfr[3], baseWs + soff);
            #pragma unroll
            for (int r = 0; r < 4; r++) {
                afr[0][r] = cvt_bits_tf32(afr[0][r]);
                afr[1][r] = cvt_bits_tf32(afr[1][r]);
                bfr[r]    = cvt_bits_tf32(bfr[r]);
            }
            #pragma unroll
            for (int i = 0; i < 2; i++) {
                mma_tf32(acc[i][0], afr[i], &bfr[0]);
                mma_tf32(acc[i][1], afr[i], &bfr[2]);
            }
        }
    }

    #pragma unroll
    for (int j = 0; j < 2; j++) {
        const int n = n0 + wn * 16 + j * 8 + 2 * qid;
        float b0 = 0.f, b1 = 0.f;
        if (bias) { b0 = bias[n]; b1 = bias[n + 1]; }
        #pragma unroll
        for (int i = 0; i < 2; i++) {
            const int m = m0 + wm * 32 + i * 16 + grp;
            float2 r0 = make_float2(acc[i][j][0] + b0, acc[i][j][1] + b1);
            float2 r1 = make_float2(acc[i][j][2] + b0, acc[i][j][3] + b1);
            if (addC) {
                float2 p0 = *(const float2*)(addC + (long)m * ldc + n);
                float2 p1 = *(const float2*)(addC + (long)(m + 8) * ldc + n);
                r0.x += p0.x; r0.y += p0.y;
                r1.x += p1.x; r1.y += p1.y;
            }
            *(float2*)(C + (long)m * ldc + n)       = r0;
            *(float2*)(C + (long)(m + 8) * ldc + n) = r1;
        }
    }
}

// ---------------------------------------------------------------------------
// Fused score + tanh + softmax + context-vector. TILE_T=4, 512 threads.
// NEW: per-warp cp.async double-buffered staging of uh s-pair rows in smem
// (no __syncthreads in score loop; per-lane wait covers per-lane reads),
// + 9-shuffle packed reduction.
// Dynamic smem: v(512) + wq(2048) + al(2048) + stage(2*16*1024) floats.
// ---------------------------------------------------------------------------
#define AT_HDR (512 * 9)                  // v + wq[4] + al[4]
#define AT_STAGE (16 * 1024)              // one buffer: 16 warps x 2 rows x 512
#define AT_SMEM_BYTES ((AT_HDR + 2 * AT_STAGE) * 4)

__global__ __launch_bounds__(512) void attn_kernel(
        const float* __restrict__ wq,
        const float* __restrict__ uh,
        const float* __restrict__ v,
        const float* __restrict__ context,
        float* __restrict__ align_out,
        float* __restrict__ c_out)
{
    extern __shared__ float sm[];
    float* v_sh  = sm;                    // [512]
    float* wq_sh = sm + 512;              // [4][512]
    float* al_sh = sm + 512 * 5;          // [4][512]
    float* ust   = sm + AT_HDR;           // [2][16][1024]

    const int b = blockIdx.y;
    const int t0 = blockIdx.x * 4;
    const int tid = threadIdx.x;
    const int warp = tid >> 5;
    const int lane = tid & 31;

    {
        v_sh[tid] = v[tid];
        #pragma unroll
        for (int tt = 0; tt < 4; tt++)
            wq_sh[tt * 512 + tid] = wq[((long)(b * T_ + t0 + tt)) * D_ + tid];
    }
    __syncthreads();

    // per-warp private staging (2 rows = 1024 floats per buffer slot)
    float* my0 = ust + warp * 1024;
    float* my1 = ust + AT_STAGE + warp * 1024;
    unsigned stAddr0 = (unsigned)__cvta_generic_to_shared(my0);
    unsigned stAddr1 = (unsigned)__cvta_generic_to_shared(my1);

    const int s0 = warp * 2;

    // prologue: stage rows (s0, s0+1) into buffer 0
    {
        const float* g = uh + ((long)(b * S_ + s0)) * D_;   // 1024 consecutive floats
        #pragma unroll
        for (int r = 0; r < 8; r++)
            cp_async16(stAddr0 + (unsigned)((lane + 32 * r) * 16),
                       g + (lane + 32 * r) * 4);
        cp_commit();
    }

    int bufsel = 0;
    for (int s = s0; s < S_; s += 32, bufsel ^= 1) {
        // prefetch next s-pair into the other buffer
        const int sn = s + 32;
        const unsigned stNext = bufsel ? stAddr0 : stAddr1;
        if (sn < S_) {
            const float* g = uh + ((long)(b * S_ + sn)) * D_;
            #pragma unroll
            for (int r = 0; r < 8; r++)
                cp_async16(stNext + (unsigned)((lane + 32 * r) * 16),
                           g + (lane + 32 * r) * 4);
        }
        cp_commit();
        cp_wait1();     // current buffer's group complete (per-lane reads own data)

        const float4* u0 = (const float4*)(bufsel ? my1 : my0);
        const float4* u1 = u0 + 128;

        float acc[2][4] = {};
        #pragma unroll
        for (int i = 0; i < 4; i++) {
            const int idx = lane + 32 * i;
            float4 x0 = u0[idx];
            float4 x1 = u1[idx];
            float4 vf = ((const float4*)v_sh)[idx];
            float4 q0 = ((const float4*)(wq_sh + 0 * 512))[idx];
            float4 q1 = ((const float4*)(wq_sh + 1 * 512))[idx];
            float4 q2 = ((const float4*)(wq_sh + 2 * 512))[idx];
            float4 q3 = ((const float4*)(wq_sh + 3 * 512))[idx];
            float u0a[4] = {x0.x, x0.y, x0.z, x0.w};
            float u1a[4] = {x1.x, x1.y, x1.z, x1.w};
            float va[4]  = {vf.x, vf.y, vf.z, vf.w};
            float qa[4][4] = {{q0.x, q0.y, q0.z, q0.w},
                              {q1.x, q1.y, q1.z, q1.w},
                              {q2.x, q2.y, q2.z, q2.w},
                              {q3.x, q3.y, q3.z, q3.w}};
            #pragma unroll
            for (int cidx = 0; cidx < 4; cidx++) {
                const float vd = va[cidx];
                #pragma unroll
                for (int tt = 0; tt < 4; tt++) {
                    acc[0][tt] = fmaf(vd, fast_tanh(u0a[cidx] + qa[tt][cidx]), acc[0][tt]);
                    acc[1][tt] = fmaf(vd, fast_tanh(u1a[cidx] + qa[tt][cidx]), acc[1][tt]);
                }
            }
        }

        // packed reduction: 8 values -> 9 shuffles; lane l<8 owns v8[l]
        float w0 = merge2(acc[0][0], acc[0][1], 1, lane);
        float w1 = merge2(acc[0][2], acc[0][3], 1, lane);
        float w2 = merge2(acc[1][0], acc[1][1], 1, lane);
        float w3 = merge2(acc[1][2], acc[1][3], 1, lane);
        float x0 = merge2(w0, w1, 2, lane);
        float x1 = merge2(w2, w3, 2, lane);
        float y  = merge2(x0, x1, 4, lane);
        y += __shfl_xor_sync(0xFFFFFFFFu, y, 8);
        y += __shfl_xor_sync(0xFFFFFFFFu, y, 16);
        if (lane < 8)
            al_sh[(lane & 3) * 512 + s + (lane >> 2)] = y;
    }
    __syncthreads();

    // ---- softmax over s: warp tt handles row t0+tt ----
    if (warp < 4) {
        float* al = al_sh + warp * 512;
        float m = -1e30f;
        for (int s = lane; s < S_; s += 32) m = fmaxf(m, al[s]);
        #pragma unroll
        for (int o = 16; o; o >>= 1)
            m = fmaxf(m, __shfl_xor_sync(0xFFFFFFFFu, m, o));
        float sum = 0.f;
        for (int s = lane; s < S_; s += 32) {
            float e = __expf(al[s] - m);
            al[s] = e;
            sum += e;
        }
        #pragma unroll
        for (int o = 16; o; o >>= 1)
            sum += __shfl_xor_sync(0xFFFFFFFFu, sum, o);
        float inv = 1.0f / sum;
        float* aout = align_out + ((long)(b * T_ + t0 + warp)) * S_;
        for (int s = lane; s < S_; s += 32) {
            float p = al[s] * inv;
            al[s] = p;
            aout[s] = p;
        }
    }
    __syncthreads();

    // ---- context vectors: c[tt][d] = sum_s p[tt][s]*context[b,s,d]; d=tid ----
    const int d = tid;
    float c0 = 0.f, c1 = 0.f, c2 = 0.f, c3 = 0.f;
    const float* cptr = context + ((long)b * S_) * D_ + d;
    #pragma unroll 4
    for (int s = 0; s < S_; s++) {
        float cx = cptr[(long)s * D_];
        c0 = fmaf(al_sh[0 * 512 + s], cx, c0);
        c1 = fmaf(al_sh[1 * 512 + s], cx, c1);
        c2 = fmaf(al_sh[2 * 512 + s], cx, c2);
        c3 = fmaf(al_sh[3 * 512 + s], cx, c3);
    }
    c_out[((long)(b * T_ + t0 + 0)) * D_ + d] = c0;
    c_out[((long)(b * T_ + t0 + 1)) * D_ + d] = c1;
    c_out[((long)(b * T_ + t0 + 2)) * D_ + d] = c2;
    c_out[((long)(b * T_ + t0 + 3)) * D_ + d] = c3;
}

// ---------------------------------------------------------------------------
extern "C" void kernel_launch(void* const* d_in, const int* in_sizes, int n_in,
                              void* d_out, int out_size)
{
    const float* inp     = (const float*)d_in[0];
    const float* context = (const float*)d_in[1];
    const float* Wq      = (const float*)d_in[2];
    const float* bq      = (const float*)d_in[3];
    const float* Wc      = (const float*)d_in[4];
    const float* v       = (const float*)d_in[5];
    const float* Wout    = (const float*)d_in[6];
    const float* bout    = (const float*)d_in[7];

    float* out    = (float*)d_out;
    float* attn_h = out;                         // (B,T,D)
    float* align  = out + (long)B_ * T_ * D_;    // (B,T,S)

    float *p_wq, *p_uh, *p_pre, *p_c;
    cudaGetSymbolAddress((void**)&p_wq, g_wq);
    cudaGetSymbolAddress((void**)&p_uh, g_uh);
    cudaGetSymbolAddress((void**)&p_pre, g_pre);
    cudaGetSymbolAddress((void**)&p_c, g_c);

    static bool attrSet = false;
    if (!attrSet) {
        cudaFuncSetAttribute(attn_kernel,
                             cudaFuncAttributeMaxDynamicSharedMemorySize,
                             AT_SMEM_BYTES);
        attrSet = true;
    }

    // ---- Launch 1: fused {wq, uh, pre} GEMMs, all K=512, BM=64 ----
    GemmArgs a1;
    a1.A[0] = inp;     a1.W[0] = Wq;          a1.bias[0] = bq;      a1.addC[0] = nullptr;
    a1.C[0] = p_wq;    a1.lda[0] = D_;        a1.ldw[0] = D_;       a1.ldc[0] = D_;
    a1.A[1] = context; a1.W[1] = Wc;          a1.bias[1] = nullptr; a1.addC[1] = nullptr;
    a1.C[1] = p_uh;    a1.lda[1] = D_;        a1.ldw[1] = D_;       a1.ldc[1] = D_;
    a1.A[2] = inp;     a1.W[2] = Wout + D_;   a1.bias[2] = bout;    a1.addC[2] = nullptr;
    a1.C[2] = p_pre;   a1.lda[2] = D_;        a1.ldw[2] = 2 * D_;   a1.ldc[2] = D_;
    a1.segEnd[0] = 8; a1.segEnd[1] = 40; a1.segEnd[2] = 48;
    gemm_seg_kernel<<<dim3(48, 8, 1), 256>>>(a1, D_);

    // ---- Launch 2: fused scores + softmax + context vectors ----
    attn_kernel<<<dim3(T_ / 4, B_), 512, AT_SMEM_BYTES>>>(
        p_wq, p_uh, v, context, align, p_c);

    // ---- Launch 3: attn_h = c @ WoutL^T + pre  (full K, epilogue fold) ----
    GemmArgs a3;
    a3.A[0] = p_c;  a3.W[0] = Wout;  a3.bias[0] = nullptr;  a3.addC[0] = p_pre;
    a3.C[0] = attn_h;
    a3.lda[0] = D_; a3.ldw[0] = 2 * D_; a3.ldc[0] = D_;
    a3.A[1] = a3.A[0]; a3.W[1] = a3.W[0]; a3.bias[1] = nullptr; a3.addC[1] = nullptr;
    a3.C[1] = a3.C[0]; a3.lda[1] = a3.lda[0]; a3.ldw[1] = a3.ldw[0]; a3.ldc[1] = a3.ldc[0];
    a3.A[2] = a3.A[0]; a3.W[2] = a3.W[0]; a3.bias[2] = nullptr; a3.addC[2] = nullptr;
    a3.C[2] = a3.C[0]; a3.lda[2] = a3.lda[0]; a3.ldw[2] = a3.ldw[0]; a3.ldc[2] = a3.ldc[0];
    a3.segEnd[0] = 8; a3.segEnd[1] = 8; a3.segEnd[2] = 8;
    gemm_seg_kernel<<<dim3(8, 8, 1), 256>>>(a3, D_);
}